// round 11
// baseline (speedup 1.0000x reference)
#include <cuda_runtime.h>
#include <cuda_fp16.h>
#include <cstdint>

#define D 128
#define MAXN 100000
#define MAXE 1600000
#define BSTR 136   // padded row stride (fp16 elems): 272B -> conflict-free ldmatrix

// ---- scratch (__device__ globals per allocation rules) ----
__device__ __half g_mh[(size_t)MAXN * D];   // m = h @ W_nb^T (fp16)
__device__ int   g_cnt[MAXN];
__device__ int   g_rowstart[MAXN];
__device__ int   g_cursor[MAXN];
__device__ int   g_scol[MAXE];
__device__ float g_sval[MAXE];
__device__ int   g_total;
__device__ int   g_is64;

// smem layout for the MMA GEMM
#define SME_B     0                         // [256][BSTR] fp16 = 69632 B
#define SME_A     69632                     // [256][BSTR] fp16 (hi rows 0-127, lo 128-255)
#define SME_STAGE 139264                    // raw fp32 tile 128x128 = 65536 B
#define SME_BIAS  204800                    // 128 floats
#define SME_TOTAL 205312

__device__ __forceinline__ uint32_t smem_u32(const void* p) {
    uint32_t a;
    asm("{ .reg .u64 t; cvta.to.shared.u64 t, %1; cvt.u32.u64 %0, t; }"
        : "=r"(a) : "l"(p));
    return a;
}

#define LDSM_X4(r0, r1, r2, r3, addr)                                          \
    asm volatile("ldmatrix.sync.aligned.m8n8.x4.shared.b16 {%0,%1,%2,%3}, [%4];" \
                 : "=r"(r0), "=r"(r1), "=r"(r2), "=r"(r3) : "r"(addr))

__device__ __forceinline__ void mma16816(float* c, const uint32_t* a,
                                         uint32_t b0, uint32_t b1) {
    asm volatile(
        "mma.sync.aligned.m16n8k16.row.col.f32.f16.f16.f32 "
        "{%0,%1,%2,%3}, {%4,%5,%6,%7}, {%8,%9}, {%0,%1,%2,%3};"
        : "+f"(c[0]), "+f"(c[1]), "+f"(c[2]), "+f"(c[3])
        : "r"(a[0]), "r"(a[1]), "r"(a[2]), "r"(a[3]), "r"(b0), "r"(b1));
}

#define CP_ASYNC16(dst, src)                                                   \
    asm volatile("cp.async.cg.shared.global [%0], [%1], 16;"                   \
                 :: "r"(dst), "l"(src) : "memory")
#define CP_COMMIT() asm volatile("cp.async.commit_group;" ::: "memory")
#define CP_WAIT0()  asm volatile("cp.async.wait_group 0;" ::: "memory")

// ---------------------------------------------------------------------------
// Persistent tensor-core dual GEMM, 2-term fp16 split, cp.async A pipeline.
//   C[128x256] = (A_hi + A_lo)[128x128] x B'[128x256]    (virtual K=256)
//   B' = fp16([W_self ; W_nb]^T);  cols 0-127 -> out(+bias), 128-255 -> g_mh
// ---------------------------------------------------------------------------
__global__ __launch_bounds__(512, 1)
void gemm_mma_kernel(const float* __restrict__ h,
                     const float* __restrict__ Wsf,
                     const float* __restrict__ bsf,
                     const float* __restrict__ Wnb,
                     const float* __restrict__ bnb,
                     float* __restrict__ out, int N, int ntiles) {
    extern __shared__ char smem[];
    const uint32_t sb = smem_u32(smem);
    const int tid = threadIdx.x;
    const int wid = tid >> 5;
    const int lane = tid & 31;
    const int wrow = (wid >> 2) * 32;
    const int wcol = (wid & 3) * 64;

    __half* sB = (__half*)(smem + SME_B);
    __half* sA = (__half*)(smem + SME_A);
    float* sbias = (float*)(smem + SME_BIAS);

    // ---- one-time: convert B' = fp16([W_self; W_nb]) directly into smem
    for (int i = tid; i < 256 * 128; i += 512) {
        int n = i >> 7, k = i & 127;
        float x = (n < 128) ? Wsf[n * D + k] : Wnb[(n - 128) * D + k];
        sB[n * BSTR + k] = __float2half_rn(x);
    }
    if (tid < D) sbias[tid] = bsf[tid] + bnb[tid];

    // helper lambdas as macros ------------------------------------------------
#define STAGE_LOAD(T)                                                          \
    do {                                                                       \
        const int _r0 = (T) * 128;                                             \
        for (int i = tid; i < 4096; i += 512) {                                \
            int row = i >> 5;                                                  \
            int coff = (i & 31) * 16;                                          \
            int r = _r0 + row;                                                 \
            uint32_t dst = sb + SME_STAGE + row * 512 + coff;                  \
            if (r < N) {                                                       \
                const char* src = (const char*)(h + (size_t)r * D) + coff;     \
                CP_ASYNC16(dst, src);                                          \
            } else {                                                           \
                *(uint4*)(smem + SME_STAGE + row * 512 + coff) =               \
                    make_uint4(0, 0, 0, 0);                                    \
            }                                                                  \
        }                                                                      \
        CP_COMMIT();                                                           \
    } while (0)

#define STAGE_CONVERT()                                                        \
    do {                                                                       \
        const float* stg = (const float*)(smem + SME_STAGE);                   \
        for (int c = tid; c < 2048; c += 512) {                                \
            int row = c >> 4, cc = c & 15;                                     \
            float4 x0 = *(const float4*)&stg[row * 128 + cc * 8];              \
            float4 x1 = *(const float4*)&stg[row * 128 + cc * 8 + 4];          \
            float xs[8] = {x0.x, x0.y, x0.z, x0.w, x1.x, x1.y, x1.z, x1.w};    \
            __half hi[8], lo[8];                                               \
            _Pragma("unroll")                                                  \
            for (int j = 0; j < 8; j++) {                                      \
                hi[j] = __float2half_rn(xs[j]);                                \
                lo[j] = __float2half_rn(xs[j] - __half2float(hi[j]));          \
            }                                                                  \
            *(uint4*)&sA[(size_t)row * BSTR + cc * 8] = *(uint4*)hi;           \
            *(uint4*)&sA[(size_t)(128 + row) * BSTR + cc * 8] = *(uint4*)lo;   \
        }                                                                      \
    } while (0)

    // ---- prologue: stage + convert first tile
    STAGE_LOAD(blockIdx.x);
    CP_WAIT0();
    __syncthreads();            // staging + B' + bias visible
    STAGE_CONVERT();
    __syncthreads();            // A' visible

    const int lrow = ((lane >> 3) & 1) * 8 + (lane & 7);
    const int lcol = (lane >> 4) * 8;

    for (int t = blockIdx.x; t < ntiles; t += gridDim.x) {
        const int r0 = t * 128;
        const int tnext = t + gridDim.x;

        // prefetch next tile's raw fp32 into staging (overlaps compute)
        if (tnext < ntiles) STAGE_LOAD(tnext);

        // ---- compute: 16 kb (8 hi + 8 lo)
        float acc[2][8][4];
#pragma unroll
        for (int mi = 0; mi < 2; mi++)
#pragma unroll
            for (int ni = 0; ni < 8; ni++)
#pragma unroll
                for (int j = 0; j < 4; j++) acc[mi][ni][j] = 0.f;

#pragma unroll
        for (int kb = 0; kb < 16; kb++) {
            const int asel = kb >> 3;          // 0: hi rows, 1: lo rows
            const int k0 = (kb & 7) * 16;

            uint32_t a[2][4];
#pragma unroll
            for (int mi = 0; mi < 2; mi++) {
                int row = asel * 128 + wrow + mi * 16 + lrow;
                uint32_t ad = sb + SME_A + (uint32_t)(row * BSTR + k0 + lcol) * 2;
                LDSM_X4(a[mi][0], a[mi][1], a[mi][2], a[mi][3], ad);
            }
            uint32_t b[4][4];
#pragma unroll
            for (int np = 0; np < 4; np++) {
                int nrow = wcol + np * 16 + lrow;
                uint32_t bd = sb + SME_B + (uint32_t)(nrow * BSTR + k0 + lcol) * 2;
                LDSM_X4(b[np][0], b[np][1], b[np][2], b[np][3], bd);
            }
#pragma unroll
            for (int mi = 0; mi < 2; mi++)
#pragma unroll
                for (int np = 0; np < 4; np++) {
                    mma16816(acc[mi][np * 2 + 0], a[mi], b[np][0], b[np][2]);
                    mma16816(acc[mi][np * 2 + 1], a[mi], b[np][1], b[np][3]);
                }
        }

        // ---- epilogue
        const int rbase = r0 + wrow + (lane >> 2);
        const int cbase = wcol + 2 * (lane & 3);

        if (wcol < 128) {
#pragma unroll
            for (int mi = 0; mi < 2; mi++)
#pragma unroll
                for (int i = 0; i < 2; i++) {
                    int r = rbase + mi * 16 + 8 * i;
                    if (r < N) {
#pragma unroll
                        for (int ni = 0; ni < 8; ni++) {
                            int c = cbase + ni * 8;
                            float2 v = make_float2(acc[mi][ni][2 * i] + sbias[c],
                                                   acc[mi][ni][2 * i + 1] + sbias[c + 1]);
                            *(float2*)&out[(size_t)r * D + c] = v;
                        }
                    }
                }
        } else {
            const int cm = cbase - 128;
#pragma unroll
            for (int mi = 0; mi < 2; mi++)
#pragma unroll
                for (int i = 0; i < 2; i++) {
                    int r = rbase + mi * 16 + 8 * i;
                    if (r < N) {
#pragma unroll
                        for (int ni = 0; ni < 8; ni++) {
                            int c = cm + ni * 8;
                            __half2 v = __floats2half2_rn(acc[mi][ni][2 * i],
                                                          acc[mi][ni][2 * i + 1]);
                            *(__half2*)&g_mh[(size_t)r * D + c] = v;
                        }
                    }
                }
        }

        // ---- rotate pipeline: convert staged t+1 into A'
        if (tnext < ntiles) {
            CP_WAIT0();
            __syncthreads();    // all warps done with A'(t) + staging complete
            STAGE_CONVERT();
            __syncthreads();    // A'(t+1) visible
        }
    }
#undef STAGE_LOAD
#undef STAGE_CONVERT
}

// ---------------------------------------------------------------------------
// CSR build
// ---------------------------------------------------------------------------
__global__ void zero_detect_kernel(const int* __restrict__ er, int N) {
    int i = blockIdx.x * blockDim.x + threadIdx.x;
    if (i < N) g_cnt[i] = 0;
    if (i == 0) {
        g_total = 0;
        int f = 1;
#pragma unroll
        for (int k = 1; k < 64; k += 2) f &= (er[k] == 0);
        g_is64 = f;
    }
}

__global__ void hist_kernel(const void* __restrict__ er, int E) {
    int base = (blockIdx.x * blockDim.x + threadIdx.x) * 4;
    const int i64 = g_is64;
    int rows[4];
#pragma unroll
    for (int j = 0; j < 4; j++) {
        int e = base + j;
        rows[j] = (e < E) ? (i64 ? (int)((const long long*)er)[e]
                                 : ((const int*)er)[e])
                          : -1;
    }
#pragma unroll
    for (int j = 0; j < 4; j++)
        if (rows[j] >= 0) atomicAdd(&g_cnt[rows[j]], 1);
}

__global__ void rowassign_kernel(int N) {
    int i = blockIdx.x * blockDim.x + threadIdx.x;
    int lane = threadIdx.x & 31;
    int v = (i < N) ? g_cnt[i] : 0;
    int s = v;
#pragma unroll
    for (int off = 1; off < 32; off <<= 1) {
        int t = __shfl_up_sync(0xFFFFFFFFu, s, off);
        if (lane >= off) s += t;
    }
    int total = __shfl_sync(0xFFFFFFFFu, s, 31);
    int base = 0;
    if (lane == 31 && total > 0) base = atomicAdd(&g_total, total);
    base = __shfl_sync(0xFFFFFFFFu, base, 31);
    if (i < N) { g_rowstart[i] = base + s - v; g_cursor[i] = 0; }
}

__global__ void bucket_kernel(const float* __restrict__ ev,
                              const void* __restrict__ er,
                              const void* __restrict__ ec,
                              int E) {
    int base = (blockIdx.x * blockDim.x + threadIdx.x) * 2;
    const int i64 = g_is64;
#pragma unroll
    for (int j = 0; j < 2; j++) {
        int e = base + j;
        if (e >= E) break;
        int row, col;
        if (i64) {
            row = (int)((const long long*)er)[e];
            col = (int)((const long long*)ec)[e];
        } else {
            row = ((const int*)er)[e];
            col = ((const int*)ec)[e];
        }
        int pos = g_rowstart[row] + atomicAdd(&g_cursor[row], 1);
        g_scol[pos] = col;
        g_sval[pos] = ev[e];
    }
}

// ---------------------------------------------------------------------------
// Aggregation over fp16 m
// ---------------------------------------------------------------------------
__global__ __launch_bounds__(256)
void aggregate_kernel(float* __restrict__ out, int N) {
    const int warp = threadIdx.x >> 5;
    const int lane = threadIdx.x & 31;
    const int r = blockIdx.x * 8 + warp;
    if (r >= N) return;

    const int start = g_rowstart[r];
    const int cnt = g_cnt[r];
    if (cnt == 0) return;

    const uint2* __restrict__ m2 = (const uint2*)g_mh;
    float4 acc = make_float4(0.f, 0.f, 0.f, 0.f);

    int i = 0;
    for (; i + 4 <= cnt; i += 4) {
        int c0 = g_scol[start + i];
        int c1 = g_scol[start + i + 1];
        int c2 = g_scol[start + i + 2];
        int c3 = g_scol[start + i + 3];
        float v0 = g_sval[start + i];
        float v1 = g_sval[start + i + 1];
        float v2 = g_sval[start + i + 2];
        float v3 = g_sval[start + i + 3];
        uint2 r0 = m2[(size_t)c0 * 32 + lane];
        uint2 r1 = m2[(size_t)c1 * 32 + lane];
        uint2 r2 = m2[(size_t)c2 * 32 + lane];
        uint2 r3 = m2[(size_t)c3 * 32 + lane];
        float2 f0a = __half22float2(*(__half2*)&r0.x);
        float2 f0b = __half22float2(*(__half2*)&r0.y);
        float2 f1a = __half22float2(*(__half2*)&r1.x);
        float2 f1b = __half22float2(*(__half2*)&r1.y);
        float2 f2a = __half22float2(*(__half2*)&r2.x);
        float2 f2b = __half22float2(*(__half2*)&r2.y);
        float2 f3a = __half22float2(*(__half2*)&r3.x);
        float2 f3b = __half22float2(*(__half2*)&r3.y);
        acc.x = fmaf(v0, f0a.x, acc.x); acc.y = fmaf(v0, f0a.y, acc.y);
        acc.z = fmaf(v0, f0b.x, acc.z); acc.w = fmaf(v0, f0b.y, acc.w);
        acc.x = fmaf(v1, f1a.x, acc.x); acc.y = fmaf(v1, f1a.y, acc.y);
        acc.z = fmaf(v1, f1b.x, acc.z); acc.w = fmaf(v1, f1b.y, acc.w);
        acc.x = fmaf(v2, f2a.x, acc.x); acc.y = fmaf(v2, f2a.y, acc.y);
        acc.z = fmaf(v2, f2b.x, acc.z); acc.w = fmaf(v2, f2b.y, acc.w);
        acc.x = fmaf(v3, f3a.x, acc.x); acc.y = fmaf(v3, f3a.y, acc.y);
        acc.z = fmaf(v3, f3b.x, acc.z); acc.w = fmaf(v3, f3b.y, acc.w);
    }
    for (; i < cnt; i++) {
        int c0 = g_scol[start + i];
        float v0 = g_sval[start + i];
        uint2 r0 = m2[(size_t)c0 * 32 + lane];
        float2 f0a = __half22float2(*(__half2*)&r0.x);
        float2 f0b = __half22float2(*(__half2*)&r0.y);
        acc.x = fmaf(v0, f0a.x, acc.x); acc.y = fmaf(v0, f0a.y, acc.y);
        acc.z = fmaf(v0, f0b.x, acc.z); acc.w = fmaf(v0, f0b.y, acc.w);
    }

    float4* op = (float4*)out + (size_t)r * 32 + lane;
    float4 o = *op;
    o.x += acc.x; o.y += acc.y; o.z += acc.z; o.w += acc.w;
    *op = o;
}

// ---------------------------------------------------------------------------
extern "C" void kernel_launch(void* const* d_in, const int* in_sizes, int n_in,
                              void* d_out, int out_size) {
    const float* h   = (const float*)d_in[0];
    const float* ev  = (const float*)d_in[1];
    const float* Wsf = (const float*)d_in[2];
    const float* bsf = (const float*)d_in[3];
    const float* Wnb = (const float*)d_in[4];
    const float* bnb = (const float*)d_in[5];
    const void*  er  = d_in[6];
    const void*  ec  = d_in[7];
    float* out = (float*)d_out;

    const int N = in_sizes[0] / D;
    const int E = in_sizes[1];
    const int nbN = (N + 255) / 256;
    const int ntiles = (N + 127) / 128;

    // one-time host-side objects (created on the non-captured correctness call)
    static cudaStream_t s_side = nullptr;
    static cudaEvent_t ev_fork = nullptr, ev_join = nullptr;
    static int n_sm = 148;
    if (s_side == nullptr) {
        cudaStreamCreateWithFlags(&s_side, cudaStreamNonBlocking);
        cudaEventCreateWithFlags(&ev_fork, cudaEventDisableTiming);
        cudaEventCreateWithFlags(&ev_join, cudaEventDisableTiming);
        cudaFuncSetAttribute(gemm_mma_kernel,
                             cudaFuncAttributeMaxDynamicSharedMemorySize, SME_TOTAL);
        cudaDeviceGetAttribute(&n_sm, cudaDevAttrMultiProcessorCount, 0);
    }

    // fork: CSR build on side stream, GEMM on main stream
    cudaEventRecord(ev_fork, 0);
    cudaStreamWaitEvent(s_side, ev_fork, 0);

    zero_detect_kernel<<<nbN, 256, 0, s_side>>>((const int*)er, N);
    hist_kernel<<<(E + 1023) / 1024, 256, 0, s_side>>>(er, E);
    rowassign_kernel<<<nbN, 256, 0, s_side>>>(N);
    bucket_kernel<<<(E + 511) / 512, 256, 0, s_side>>>(ev, er, ec, E);
    cudaEventRecord(ev_join, s_side);

    const int ngrid = (ntiles < n_sm) ? ntiles : n_sm;
    gemm_mma_kernel<<<ngrid, 512, SME_TOTAL>>>(h, Wsf, bsf, Wnb, bnb, out, N, ntiles);

    // join: aggregate needs both branches
    cudaStreamWaitEvent(0, ev_join, 0);
    aggregate_kernel<<<(N + 7) / 8, 256>>>(out, N);
}

// round 13
// speedup vs baseline: 1.3611x; 1.3611x over previous
#include <cuda_runtime.h>
#include <cuda_fp16.h>
#include <cstdint>

#define D 128
#define MAXN 100000
#define MAXE 1600000
#define BSTR 136   // padded row stride (fp16 elems): 272B -> conflict-free ldmatrix

// ---- scratch (__device__ globals per allocation rules) ----
__device__ __half g_mh[(size_t)MAXN * D];   // m = h @ W_nb^T (fp16)
__device__ int   g_cnt[MAXN];
__device__ int   g_rowstart[MAXN];
__device__ int   g_cursor[MAXN];
__device__ int   g_scol[MAXE];
__device__ float g_sval[MAXE];
__device__ int   g_total;
__device__ int   g_is64;

// smem layout for the MMA GEMM
#define SME_B    0                          // [256][BSTR] fp16 = 69632 B
#define SME_A    69632                      // [256][BSTR] fp16 (hi rows 0-127, lo 128-255)
#define SME_BIAS 139264                     // 128 floats
#define SME_TOTAL 139776

__device__ __forceinline__ uint32_t smem_u32(const void* p) {
    uint32_t a;
    asm("{ .reg .u64 t; cvta.to.shared.u64 t, %1; cvt.u32.u64 %0, t; }"
        : "=r"(a) : "l"(p));
    return a;
}

#define LDSM_X4(r0, r1, r2, r3, addr)                                          \
    asm volatile("ldmatrix.sync.aligned.m8n8.x4.shared.b16 {%0,%1,%2,%3}, [%4];" \
                 : "=r"(r0), "=r"(r1), "=r"(r2), "=r"(r3) : "r"(addr))

__device__ __forceinline__ void mma16816(float* c, const uint32_t* a,
                                         uint32_t b0, uint32_t b1) {
    asm volatile(
        "mma.sync.aligned.m16n8k16.row.col.f32.f16.f16.f32 "
        "{%0,%1,%2,%3}, {%4,%5,%6,%7}, {%8,%9}, {%0,%1,%2,%3};"
        : "+f"(c[0]), "+f"(c[1]), "+f"(c[2]), "+f"(c[3])
        : "r"(a[0]), "r"(a[1]), "r"(a[2]), "r"(a[3]), "r"(b0), "r"(b1));
}

// ---------------------------------------------------------------------------
// Persistent tensor-core dual GEMM, 2-term fp16 split (R10 structure):
//   C[128x256] = (A_hi + A_lo)[128x128] x B'[128x256]     (virtual K=256)
//   B' = fp16([W_self ; W_nb]); cols 0-127 -> out(+bias), 128-255 -> g_mh
// B' converted once per CTA in the prologue; CTA loops over 128-row tiles.
// ---------------------------------------------------------------------------
__global__ __launch_bounds__(512, 1)
void gemm_mma_kernel(const float* __restrict__ h,
                     const float* __restrict__ Wsf,
                     const float* __restrict__ bsf,
                     const float* __restrict__ Wnb,
                     const float* __restrict__ bnb,
                     float* __restrict__ out, int N, int ntiles) {
    extern __shared__ char smem[];
    const uint32_t sb = smem_u32(smem);
    const int tid = threadIdx.x;
    const int wid = tid >> 5;
    const int lane = tid & 31;
    const int wrow = (wid >> 2) * 32;
    const int wcol = (wid & 3) * 64;

    __half* sB = (__half*)(smem + SME_B);
    __half* sA = (__half*)(smem + SME_A);
    float* sbias = (float*)(smem + SME_BIAS);

    // ---- one-time: B' = fp16([W_self ; W_nb]) converted straight into smem
    for (int i = tid; i < 256 * 128; i += 512) {
        int n = i >> 7, k = i & 127;
        float x = (n < 128) ? Wsf[n * D + k] : Wnb[(n - 128) * D + k];
        sB[n * BSTR + k] = __float2half_rn(x);
    }
    if (tid < D) sbias[tid] = bsf[tid] + bnb[tid];

    const int lrow = ((lane >> 3) & 1) * 8 + (lane & 7);
    const int lcol = (lane >> 4) * 8;

    for (int t = blockIdx.x; t < ntiles; t += gridDim.x) {
        const int r0 = t * 128;

        __syncthreads();   // prev tile's ldmatrix reads done (and B'/bias, 1st iter)

        // ---- load h tile, split fp16 hi/lo into A' smem (direct LDG, R10 style)
        for (int c = tid; c < 2048; c += 512) {
            int row = c >> 4, cc = c & 15;
            int r = r0 + row;
            float xs[8] = {0.f, 0.f, 0.f, 0.f, 0.f, 0.f, 0.f, 0.f};
            if (r < N) {
                float4 x0 = *(const float4*)&h[(size_t)r * D + cc * 8];
                float4 x1 = *(const float4*)&h[(size_t)r * D + cc * 8 + 4];
                xs[0] = x0.x; xs[1] = x0.y; xs[2] = x0.z; xs[3] = x0.w;
                xs[4] = x1.x; xs[5] = x1.y; xs[6] = x1.z; xs[7] = x1.w;
            }
            __half hi[8], lo[8];
#pragma unroll
            for (int j = 0; j < 8; j++) {
                hi[j] = __float2half_rn(xs[j]);
                lo[j] = __float2half_rn(xs[j] - __half2float(hi[j]));
            }
            *(uint4*)&sA[(size_t)row * BSTR + cc * 8] = *(uint4*)hi;
            *(uint4*)&sA[(size_t)(128 + row) * BSTR + cc * 8] = *(uint4*)lo;
        }
        __syncthreads();

        // ---- compute: 16 kb (8 hi + 8 lo), single B image
        float acc[2][8][4];
#pragma unroll
        for (int mi = 0; mi < 2; mi++)
#pragma unroll
            for (int ni = 0; ni < 8; ni++)
#pragma unroll
                for (int j = 0; j < 4; j++) acc[mi][ni][j] = 0.f;

#pragma unroll
        for (int kb = 0; kb < 16; kb++) {
            const int asel = kb >> 3;          // 0: hi rows, 1: lo rows
            const int k0 = (kb & 7) * 16;

            uint32_t a[2][4];
#pragma unroll
            for (int mi = 0; mi < 2; mi++) {
                int row = asel * 128 + wrow + mi * 16 + lrow;
                uint32_t ad = sb + SME_A + (uint32_t)(row * BSTR + k0 + lcol) * 2;
                LDSM_X4(a[mi][0], a[mi][1], a[mi][2], a[mi][3], ad);
            }
            uint32_t b[4][4];
#pragma unroll
            for (int np = 0; np < 4; np++) {
                int nrow = wcol + np * 16 + lrow;
                uint32_t bd = sb + SME_B + (uint32_t)(nrow * BSTR + k0 + lcol) * 2;
                LDSM_X4(b[np][0], b[np][1], b[np][2], b[np][3], bd);
            }
#pragma unroll
            for (int mi = 0; mi < 2; mi++)
#pragma unroll
                for (int np = 0; np < 4; np++) {
                    mma16816(acc[mi][np * 2 + 0], a[mi], b[np][0], b[np][2]);
                    mma16816(acc[mi][np * 2 + 1], a[mi], b[np][1], b[np][3]);
                }
        }

        // ---- epilogue
        const int rbase = r0 + wrow + (lane >> 2);
        const int cbase = wcol + 2 * (lane & 3);

        if (wcol < 128) {
#pragma unroll
            for (int mi = 0; mi < 2; mi++)
#pragma unroll
                for (int i = 0; i < 2; i++) {
                    int r = rbase + mi * 16 + 8 * i;
                    if (r < N) {
#pragma unroll
                        for (int ni = 0; ni < 8; ni++) {
                            int c = cbase + ni * 8;
                            float2 v = make_float2(acc[mi][ni][2 * i] + sbias[c],
                                                   acc[mi][ni][2 * i + 1] + sbias[c + 1]);
                            *(float2*)&out[(size_t)r * D + c] = v;
                        }
                    }
                }
        } else {
            const int cm = cbase - 128;
#pragma unroll
            for (int mi = 0; mi < 2; mi++)
#pragma unroll
                for (int i = 0; i < 2; i++) {
                    int r = rbase + mi * 16 + 8 * i;
                    if (r < N) {
#pragma unroll
                        for (int ni = 0; ni < 8; ni++) {
                            int c = cm + ni * 8;
                            __half2 v = __floats2half2_rn(acc[mi][ni][2 * i],
                                                          acc[mi][ni][2 * i + 1]);
                            *(__half2*)&g_mh[(size_t)r * D + c] = v;
                        }
                    }
                }
        }
    }
}

// ---------------------------------------------------------------------------
// CSR build
// ---------------------------------------------------------------------------
__global__ void zero_detect_kernel(const int* __restrict__ er, int N) {
    int i = blockIdx.x * blockDim.x + threadIdx.x;
    if (i < N) g_cnt[i] = 0;
    if (i == 0) {
        g_total = 0;
        int f = 1;
#pragma unroll
        for (int k = 1; k < 64; k += 2) f &= (er[k] == 0);
        g_is64 = f;
    }
}

__global__ void hist_kernel(const void* __restrict__ er, int E) {
    int base = (blockIdx.x * blockDim.x + threadIdx.x) * 4;
    const int i64 = g_is64;
    int rows[4];
#pragma unroll
    for (int j = 0; j < 4; j++) {
        int e = base + j;
        rows[j] = (e < E) ? (i64 ? (int)((const long long*)er)[e]
                                 : ((const int*)er)[e])
                          : -1;
    }
#pragma unroll
    for (int j = 0; j < 4; j++)
        if (rows[j] >= 0) atomicAdd(&g_cnt[rows[j]], 1);
}

__global__ void rowassign_kernel(int N) {
    int i = blockIdx.x * blockDim.x + threadIdx.x;
    int lane = threadIdx.x & 31;
    int v = (i < N) ? g_cnt[i] : 0;
    int s = v;
#pragma unroll
    for (int off = 1; off < 32; off <<= 1) {
        int t = __shfl_up_sync(0xFFFFFFFFu, s, off);
        if (lane >= off) s += t;
    }
    int total = __shfl_sync(0xFFFFFFFFu, s, 31);
    int base = 0;
    if (lane == 31 && total > 0) base = atomicAdd(&g_total, total);
    base = __shfl_sync(0xFFFFFFFFu, base, 31);
    if (i < N) { g_rowstart[i] = base + s - v; g_cursor[i] = 0; }
}

__global__ void bucket_kernel(const float* __restrict__ ev,
                              const void* __restrict__ er,
                              const void* __restrict__ ec,
                              int E) {
    int base = (blockIdx.x * blockDim.x + threadIdx.x) * 2;
    const int i64 = g_is64;
#pragma unroll
    for (int j = 0; j < 2; j++) {
        int e = base + j;
        if (e >= E) break;
        int row, col;
        if (i64) {
            row = (int)((const long long*)er)[e];
            col = (int)((const long long*)ec)[e];
        } else {
            row = ((const int*)er)[e];
            col = ((const int*)ec)[e];
        }
        int pos = g_rowstart[row] + atomicAdd(&g_cursor[row], 1);
        g_scol[pos] = col;
        g_sval[pos] = ev[e];
    }
}

// ---------------------------------------------------------------------------
// Aggregation over fp16 m
// ---------------------------------------------------------------------------
__global__ __launch_bounds__(256)
void aggregate_kernel(float* __restrict__ out, int N) {
    const int warp = threadIdx.x >> 5;
    const int lane = threadIdx.x & 31;
    const int r = blockIdx.x * 8 + warp;
    if (r >= N) return;

    const int start = g_rowstart[r];
    const int cnt = g_cnt[r];
    if (cnt == 0) return;

    const uint2* __restrict__ m2 = (const uint2*)g_mh;
    float4 acc = make_float4(0.f, 0.f, 0.f, 0.f);

    int i = 0;
    for (; i + 4 <= cnt; i += 4) {
        int c0 = g_scol[start + i];
        int c1 = g_scol[start + i + 1];
        int c2 = g_scol[start + i + 2];
        int c3 = g_scol[start + i + 3];
        float v0 = g_sval[start + i];
        float v1 = g_sval[start + i + 1];
        float v2 = g_sval[start + i + 2];
        float v3 = g_sval[start + i + 3];
        uint2 r0 = m2[(size_t)c0 * 32 + lane];
        uint2 r1 = m2[(size_t)c1 * 32 + lane];
        uint2 r2 = m2[(size_t)c2 * 32 + lane];
        uint2 r3 = m2[(size_t)c3 * 32 + lane];
        float2 f0a = __half22float2(*(__half2*)&r0.x);
        float2 f0b = __half22float2(*(__half2*)&r0.y);
        float2 f1a = __half22float2(*(__half2*)&r1.x);
        float2 f1b = __half22float2(*(__half2*)&r1.y);
        float2 f2a = __half22float2(*(__half2*)&r2.x);
        float2 f2b = __half22float2(*(__half2*)&r2.y);
        float2 f3a = __half22float2(*(__half2*)&r3.x);
        float2 f3b = __half22float2(*(__half2*)&r3.y);
        acc.x = fmaf(v0, f0a.x, acc.x); acc.y = fmaf(v0, f0a.y, acc.y);
        acc.z = fmaf(v0, f0b.x, acc.z); acc.w = fmaf(v0, f0b.y, acc.w);
        acc.x = fmaf(v1, f1a.x, acc.x); acc.y = fmaf(v1, f1a.y, acc.y);
        acc.z = fmaf(v1, f1b.x, acc.z); acc.w = fmaf(v1, f1b.y, acc.w);
        acc.x = fmaf(v2, f2a.x, acc.x); acc.y = fmaf(v2, f2a.y, acc.y);
        acc.z = fmaf(v2, f2b.x, acc.z); acc.w = fmaf(v2, f2b.y, acc.w);
        acc.x = fmaf(v3, f3a.x, acc.x); acc.y = fmaf(v3, f3a.y, acc.y);
        acc.z = fmaf(v3, f3b.x, acc.z); acc.w = fmaf(v3, f3b.y, acc.w);
    }
    for (; i < cnt; i++) {
        int c0 = g_scol[start + i];
        float v0 = g_sval[start + i];
        uint2 r0 = m2[(size_t)c0 * 32 + lane];
        float2 f0a = __half22float2(*(__half2*)&r0.x);
        float2 f0b = __half22float2(*(__half2*)&r0.y);
        acc.x = fmaf(v0, f0a.x, acc.x); acc.y = fmaf(v0, f0a.y, acc.y);
        acc.z = fmaf(v0, f0b.x, acc.z); acc.w = fmaf(v0, f0b.y, acc.w);
    }

    float4* op = (float4*)out + (size_t)r * 32 + lane;
    float4 o = *op;
    o.x += acc.x; o.y += acc.y; o.z += acc.z; o.w += acc.w;
    *op = o;
}

// ---------------------------------------------------------------------------
extern "C" void kernel_launch(void* const* d_in, const int* in_sizes, int n_in,
                              void* d_out, int out_size) {
    const float* h   = (const float*)d_in[0];
    const float* ev  = (const float*)d_in[1];
    const float* Wsf = (const float*)d_in[2];
    const float* bsf = (const float*)d_in[3];
    const float* Wnb = (const float*)d_in[4];
    const float* bnb = (const float*)d_in[5];
    const void*  er  = d_in[6];
    const void*  ec  = d_in[7];
    float* out = (float*)d_out;

    const int N = in_sizes[0] / D;
    const int E = in_sizes[1];
    const int nbN = (N + 255) / 256;
    const int ntiles = (N + 127) / 128;

    // one-time host-side objects (created on the non-captured correctness call)
    static cudaStream_t s_side = nullptr;
    static cudaEvent_t ev_fork = nullptr, ev_join = nullptr;
    static int n_sm = 148;
    if (s_side == nullptr) {
        cudaStreamCreateWithFlags(&s_side, cudaStreamNonBlocking);
        cudaEventCreateWithFlags(&ev_fork, cudaEventDisableTiming);
        cudaEventCreateWithFlags(&ev_join, cudaEventDisableTiming);
        cudaFuncSetAttribute(gemm_mma_kernel,
                             cudaFuncAttributeMaxDynamicSharedMemorySize, SME_TOTAL);
        cudaDeviceGetAttribute(&n_sm, cudaDevAttrMultiProcessorCount, 0);
    }

    // fork: CSR build on side stream, GEMM on main stream
    cudaEventRecord(ev_fork, 0);
    cudaStreamWaitEvent(s_side, ev_fork, 0);

    zero_detect_kernel<<<nbN, 256, 0, s_side>>>((const int*)er, N);
    hist_kernel<<<(E + 1023) / 1024, 256, 0, s_side>>>(er, E);
    rowassign_kernel<<<nbN, 256, 0, s_side>>>(N);
    bucket_kernel<<<(E + 511) / 512, 256, 0, s_side>>>(ev, er, ec, E);
    cudaEventRecord(ev_join, s_side);

    const int ngrid = (ntiles < n_sm) ? ntiles : n_sm;
    gemm_mma_kernel<<<ngrid, 512, SME_TOTAL>>>(h, Wsf, bsf, Wnb, bnb, out, N, ntiles);

    // join: aggregate needs both branches
    cudaStreamWaitEvent(0, ev_join, 0);
    aggregate_kernel<<<(N + 7) / 8, 256>>>(out, N);
}